// round 10
// baseline (speedup 1.0000x reference)
#include <cuda_runtime.h>
#include <cuda_fp16.h>
#include <cstdint>

// ---------------------------------------------------------------------------
// HTSubTree, 2-kernel pipeline (fp16 operands, fp32 accumulation):
//   ht_prep : W01h[(o01*8+r02)][i01] (512x64 fp16)
//             Vth[n=(o23*8+r04)][k=(r02*64+i23)] (512x512 fp16)
//   ht_fused: grid 1024, unit = 32 out rows (b = blk>>1, o01 in [q*32,+32)):
//       Phase A: Ah[32][512] fp16 in SMEM = T rows (W01h slice @ X_b^T)
//       Phase B: out[32][512] = Ah @ Vth^T  (2 n-blocks x 8 k-chunks, 2-stage)
// mma.sync m16n8k16 row.col: A[m][k] row-major, B stored [n][k] n-major.
// ---------------------------------------------------------------------------

__device__ __half g_W01h[512 * 64];
__device__ __half g_Vth[512 * 512];

// ---------------- helpers --------------------------------------------------
__device__ __forceinline__ uint32_t smem_u32(const void* p) {
    uint32_t a;
    asm("{ .reg .u64 t; cvta.to.shared.u64 t, %1; cvt.u32.u64 %0, t; }" : "=r"(a) : "l"(p));
    return a;
}
__device__ __forceinline__ void cp16(uint32_t s, const void* g) {
    asm volatile("cp.async.cg.shared.global [%0], [%1], 16;" :: "r"(s), "l"(g) : "memory");
}
__device__ __forceinline__ void cp_commit() { asm volatile("cp.async.commit_group;" ::: "memory"); }
__device__ __forceinline__ void cp_wait0()  { asm volatile("cp.async.wait_group 0;" ::: "memory"); }
__device__ __forceinline__ void cp_wait1()  { asm volatile("cp.async.wait_group 1;" ::: "memory"); }

__device__ __forceinline__ void mma16(float& d0, float& d1, float& d2, float& d3,
                                      uint32_t a0, uint32_t a1, uint32_t a2, uint32_t a3,
                                      uint32_t b0, uint32_t b1) {
    asm volatile(
        "mma.sync.aligned.m16n8k16.row.col.f32.f16.f16.f32 "
        "{%0,%1,%2,%3}, {%4,%5,%6,%7}, {%8,%9}, {%0,%1,%2,%3};"
        : "+f"(d0), "+f"(d1), "+f"(d2), "+f"(d3)
        : "r"(a0), "r"(a1), "r"(a2), "r"(a3), "r"(b0), "r"(b1));
}
__device__ __forceinline__ void ldsm4(uint32_t& r0, uint32_t& r1, uint32_t& r2,
                                      uint32_t& r3, uint32_t addr) {
    asm volatile("ldmatrix.sync.aligned.m8n8.x4.shared.b16 {%0,%1,%2,%3}, [%4];"
                 : "=r"(r0), "=r"(r1), "=r"(r2), "=r"(r3) : "r"(addr));
}

// ---------------------------------------------------------------------------
// ht_prep: grid 64 (one CTA per o23), 256 threads.  (R9-proven)
// ---------------------------------------------------------------------------
__global__ void ht_prep(const float* __restrict__ factors,
                        const float* __restrict__ cores) {
    __shared__ float sf[2048];
    __shared__ float sc[1536];
    __shared__ float w23s[512];      // [i23][r24] for this o23
    const int tid = threadIdx.x, blk = blockIdx.x;   // blk = o23
    for (int i = tid; i < 2048; i += 256) sf[i] = factors[i];
    for (int i = tid; i < 1536; i += 256) sc[i] = cores[i];
    __syncthreads();

    #pragma unroll
    for (int j = 0; j < 2; ++j) {
        int e = blk * 512 + j * 256 + tid;
        int row = e >> 6, i01 = e & 63;
        int o01 = row >> 3, r02 = row & 7;
        int o0 = o01 >> 3, o1 = o01 & 7, i0 = i01 >> 3, i1 = i01 & 7;
        const float* F0 = sf + i0 * 64 + o0 * 8;
        const float* F1 = sf + 512 + i1 * 64 + o1 * 8;
        const float* C02 = sc + 512;
        float acc = 0.f;
        #pragma unroll
        for (int r01 = 0; r01 < 8; ++r01) {
            float s = 0.f;
            #pragma unroll
            for (int r12 = 0; r12 < 8; ++r12)
                s += F1[r12] * C02[r01 * 64 + r12 * 8 + r02];
            acc += F0[r01] * s;
        }
        g_W01h[e] = __float2half_rn(acc);
    }

    const int o2 = blk >> 3, o3 = blk & 7;
    #pragma unroll
    for (int j = 0; j < 2; ++j) {
        int t = tid + j * 256;
        int i23 = t >> 3, r24 = t & 7;
        int i2 = i23 >> 3, i3 = i23 & 7;
        const float* F2 = sf + 1024 + i2 * 64 + o2 * 8;
        const float* F3 = sf + 1536 + i3 * 64 + o3 * 8;
        const float* C24 = sc + 1024;
        float acc = 0.f;
        #pragma unroll
        for (int r23 = 0; r23 < 8; ++r23) {
            float s = 0.f;
            #pragma unroll
            for (int r34 = 0; r34 < 8; ++r34)
                s += F3[r34] * C24[r23 * 64 + r34 * 8 + r24];
            acc += F2[r23] * s;
        }
        w23s[t] = acc;
    }
    __syncthreads();

    const float* C04 = sc;
    #pragma unroll
    for (int it = 0; it < 16; ++it) {
        int idx = it * 256 + tid;
        int r02 = idx >> 9, rem = idx & 511;
        int i23 = rem >> 3, r04 = rem & 7;
        const float* w = w23s + i23 * 8;
        const float* c = C04 + r02 * 64 + r04;
        float acc = 0.f;
        #pragma unroll
        for (int r24 = 0; r24 < 8; ++r24) acc += w[r24] * c[r24 * 8];
        int n = blk * 8 + r04, k = r02 * 64 + i23;
        g_Vth[(size_t)n * 512 + k] = __float2half_rn(acc);
    }
}

// ---------------------------------------------------------------------------
// ht_fused: grid 1024, 256 threads = 8 warps, 2 CTAs/SM.
// SMEM map (bytes):
//   [0, 33280)           Ah half[32][520]
//   [33280, 107008)      D region:
//     phase A: W half[256][72] (36864) | Xh half[64][72] (9216)
//     phase B: 2 stages x B half[256][72] (36864 each)
// ---------------------------------------------------------------------------
#define AH_STRIDE 520
#define AH_BYTES  (32 * AH_STRIDE * 2)           // 33280
#define D_OFF     AH_BYTES
#define XH_OFF    (D_OFF + 256 * 72 * 2)         // 33280 + 36864
#define STG_BYTES (256 * 72 * 2)                 // 36864
#define FUSED_SMEM (AH_BYTES + 2 * STG_BYTES)    // 107008

__device__ __forceinline__ void fused_loadB(uint32_t sbase, int g, int tid) {
    int nb = g >> 3, c = g & 7;
    const __half* Bg = g_Vth + (size_t)(nb * 256) * 512 + c * 64;
    uint32_t ab = sbase + D_OFF + (uint32_t)(g & 1) * STG_BYTES;
    #pragma unroll
    for (int i = 0; i < 8; ++i) {
        int l = tid + i * 256;
        int row = l >> 3, s16 = (l & 7) * 8;
        cp16(ab + (uint32_t)(row * 72 + s16) * 2, Bg + (size_t)row * 512 + s16);
    }
    cp_commit();
}

__global__ __launch_bounds__(256, 2) void ht_fused(float* __restrict__ C,
                                                   const float* __restrict__ x) {
    extern __shared__ char smc[];
    uint32_t sbase = smem_u32(smc);
    const int tid = threadIdx.x, wid = tid >> 5, lane = tid & 31;
    const int gid = lane >> 2, tig = lane & 3;
    const int blk = blockIdx.x;
    const int mBase = blk * 32;
    const int b = blk >> 1, q = blk & 1;

    // ---- Phase A loads ----------------------------------------------------
    // W01h slice rows [q*256, +256) via cp.async, stride-72 rows
    const __half* Wg = g_W01h + (size_t)(q * 256) * 64;
    #pragma unroll
    for (int i = 0; i < 8; ++i) {
        int l = tid + i * 256;
        int row = l >> 3, s16 = (l & 7) * 8;
        cp16(sbase + D_OFF + (uint32_t)(row * 72 + s16) * 2, Wg + row * 64 + s16);
    }
    cp_commit();
    // X_b: LDG (coalesced along i23) -> fp16 transposed into Xh[64][72]
    {
        const float* xb = x + (size_t)b * 4096;
        __half* Xh = (__half*)(smc + XH_OFF);
        #pragma unroll
        for (int i = 0; i < 8; ++i) {
            int l = tid + i * 256;
            int i23 = l & 63, i01p = (l >> 6) * 2;
            float v0 = __ldg(xb + i01p * 64 + i23);
            float v1 = __ldg(xb + (i01p + 1) * 64 + i23);
            *(__half2*)(Xh + i23 * 72 + i01p) = __floats2half2_rn(v0, v1);
        }
    }
    cp_wait0();
    __syncthreads();

    // ---- Phase A mma: Rp[256 rows (o01_local,r02)][64 i23] ----------------
    // warp strip: rows pp*128 + wid*16 .. +16, all 64 i23 cols
    const uint32_t aoffA = (uint32_t)D_OFF +
        ((uint32_t)(((lane & 7) + ((lane >> 3) & 1) * 8) * 72
                    + ((lane >> 4) & 1) * 8)) * 2;
    const uint32_t boffA = (uint32_t)XH_OFF +
        ((uint32_t)(((lane & 7) + ((lane >> 4) & 1) * 8) * 72
                    + ((lane >> 3) & 1) * 8)) * 2;

    #pragma unroll
    for (int pp = 0; pp < 2; ++pp) {
        const int rowbase = pp * 128 + wid * 16;
        float accA[8][4];
        #pragma unroll
        for (int nt = 0; nt < 8; ++nt)
            #pragma unroll
            for (int qq = 0; qq < 4; ++qq) accA[nt][qq] = 0.f;

        #pragma unroll
        for (int s = 0; s < 4; ++s) {
            const uint32_t kb = (uint32_t)(s * 32);
            uint32_t a0, a1, a2, a3, bf[4][4];
            ldsm4(a0, a1, a2, a3,
                  sbase + aoffA + (uint32_t)(rowbase * 72 * 2) + kb);
            #pragma unroll
            for (int p = 0; p < 4; ++p)
                ldsm4(bf[p][0], bf[p][1], bf[p][2], bf[p][3],
                      sbase + boffA + (uint32_t)(p * 16 * 72 * 2) + kb);
            #pragma unroll
            for (int p = 0; p < 4; ++p) {
                mma16(accA[2*p][0], accA[2*p][1], accA[2*p][2], accA[2*p][3],
                      a0, a1, a2, a3, bf[p][0], bf[p][1]);
                mma16(accA[2*p+1][0], accA[2*p+1][1], accA[2*p+1][2], accA[2*p+1][3],
                      a0, a1, a2, a3, bf[p][2], bf[p][3]);
            }
        }

        // scatter into Ah: Rp-row rowp=(o01_local*8+r02) -> Ah[rowp>>3][(rowp&7)*64+i23]
        const int row0 = rowbase + gid, row1 = rowbase + gid + 8;
        const int ar0 = row0 >> 3, cb0 = (row0 & 7) * 64;
        const int ar1 = row1 >> 3, cb1 = (row1 & 7) * 64;
        #pragma unroll
        for (int nt = 0; nt < 8; ++nt) {
            int i23 = nt * 8 + 2 * tig;
            *(__half2*)(smc + (ar0 * AH_STRIDE + cb0 + i23) * 2) =
                __floats2half2_rn(accA[nt][0], accA[nt][1]);
            *(__half2*)(smc + (ar1 * AH_STRIDE + cb1 + i23) * 2) =
                __floats2half2_rn(accA[nt][2], accA[nt][3]);
        }
    }
    __syncthreads();   // Ah complete; D region free for B staging

    // ---- Phase B: out[32][512] = Ah @ Vth^T -------------------------------
    // 2 n-blocks (256) x 8 k-chunks (BK=64), 2-stage cp.async.
    // warp tile 32m x 32n (wn = wid)
    const uint32_t aoffB =
        ((uint32_t)(((lane & 7) + ((lane >> 3) & 1) * 8) * AH_STRIDE
                    + ((lane >> 4) & 1) * 8)) * 2;
    const uint32_t boffB =
        ((uint32_t)((wid * 32 + (lane & 7) + ((lane >> 4) & 1) * 8) * 72
                    + ((lane >> 3) & 1) * 8)) * 2;

    float acc[2][4][4];
    #pragma unroll
    for (int mt = 0; mt < 2; ++mt)
        #pragma unroll
        for (int nt = 0; nt < 4; ++nt)
            #pragma unroll
            for (int qq = 0; qq < 4; ++qq) acc[mt][nt][qq] = 0.f;

    fused_loadB(sbase, 0, tid);
    fused_loadB(sbase, 1, tid);

    #pragma unroll 1
    for (int g = 0; g < 16; ++g) {
        if (g == 15) cp_wait0(); else cp_wait1();
        __syncthreads();

        const int c = g & 7;
        const uint32_t stb = sbase + D_OFF + (uint32_t)(g & 1) * STG_BYTES;
        #pragma unroll
        for (int s = 0; s < 4; ++s) {
            const uint32_t kbA = (uint32_t)((c * 64 + s * 16) * 2);
            const uint32_t kbB = (uint32_t)(s * 32);
            uint32_t a[2][4], bf[2][4];
            ldsm4(a[0][0], a[0][1], a[0][2], a[0][3], sbase + aoffB + kbA);
            ldsm4(a[1][0], a[1][1], a[1][2], a[1][3],
                  sbase + aoffB + kbA + (uint32_t)(16 * AH_STRIDE * 2));
            #pragma unroll
            for (int p = 0; p < 2; ++p)
                ldsm4(bf[p][0], bf[p][1], bf[p][2], bf[p][3],
                      stb + boffB + kbB + (uint32_t)(p * 16 * 72 * 2));
            #pragma unroll
            for (int p = 0; p < 2; ++p) {
                #pragma unroll
                for (int mt = 0; mt < 2; ++mt) {
                    mma16(acc[mt][2*p][0], acc[mt][2*p][1], acc[mt][2*p][2], acc[mt][2*p][3],
                          a[mt][0], a[mt][1], a[mt][2], a[mt][3], bf[p][0], bf[p][1]);
                    mma16(acc[mt][2*p+1][0], acc[mt][2*p+1][1], acc[mt][2*p+1][2], acc[mt][2*p+1][3],
                          a[mt][0], a[mt][1], a[mt][2], a[mt][3], bf[p][2], bf[p][3]);
                }
            }
        }
        __syncthreads();
        if (g + 2 < 16) fused_loadB(sbase, g + 2, tid);

        if (c == 7) {
            const int nBase = (g >> 3) * 256;
            #pragma unroll
            for (int mt = 0; mt < 2; ++mt) {
                int r0 = mBase + mt * 16 + gid;
                #pragma unroll
                for (int nt = 0; nt < 4; ++nt) {
                    int col = nBase + wid * 32 + nt * 8 + 2 * tig;
                    *(float2*)(C + (size_t)r0 * 512 + col) =
                        make_float2(acc[mt][nt][0], acc[mt][nt][1]);
                    *(float2*)(C + (size_t)(r0 + 8) * 512 + col) =
                        make_float2(acc[mt][nt][2], acc[mt][nt][3]);
                    #pragma unroll
                    for (int qq = 0; qq < 4; ++qq) acc[mt][nt][qq] = 0.f;
                }
            }
        }
    }
}

// ---------------------------------------------------------------------------
extern "C" void kernel_launch(void* const* d_in, const int* in_sizes, int n_in,
                              void* d_out, int out_size) {
    (void)in_sizes; (void)n_in; (void)out_size;
    const float* x       = (const float*)d_in[0];
    const float* factors = (const float*)d_in[1];
    const float* cores   = (const float*)d_in[2];
    float* out = (float*)d_out;

    cudaFuncSetAttribute(ht_fused, cudaFuncAttributeMaxDynamicSharedMemorySize,
                         FUSED_SMEM);

    ht_prep<<<64, 256>>>(factors, cores);
    ht_fused<<<1024, 256, FUSED_SMEM>>>(out, x);
}

// round 12
// speedup vs baseline: 1.2655x; 1.2655x over previous
#include <cuda_runtime.h>
#include <cuda_fp16.h>
#include <cstdint>

// ---------------------------------------------------------------------------
// HTSubTree, 3-kernel pipeline (fp16 operands, fp32 accumulation):
//   ht_prep : W01h[(o01*8+r02)][i01] (512x64 fp16)
//             Vth[n=(o23*8+r04)][k=(r02*64+i23)] (512x512 fp16)
//   ht_k1m  : Th[b*64+o01][r02*64+i23] = W01h @ X_b^T   (persistent, 4 b/CTA)
//   ht_k2m  : out[b*64+o01][n] = Th @ Vth^T             (R6-proven geometry)
// mma.sync m16n8k16 row.col: A[m][k] row-major, B stored [n][k] n-major.
// ---------------------------------------------------------------------------

__device__ __half g_W01h[512 * 64];
__device__ __half g_Vth[512 * 512];
__device__ __half g_Th[32768 * 512];

// ---------------- helpers --------------------------------------------------
__device__ __forceinline__ uint32_t smem_u32(const void* p) {
    uint32_t a;
    asm("{ .reg .u64 t; cvta.to.shared.u64 t, %1; cvt.u32.u64 %0, t; }" : "=r"(a) : "l"(p));
    return a;
}
__device__ __forceinline__ void cp16(uint32_t s, const void* g) {
    asm volatile("cp.async.cg.shared.global [%0], [%1], 16;" :: "r"(s), "l"(g) : "memory");
}
__device__ __forceinline__ void cp_commit() { asm volatile("cp.async.commit_group;" ::: "memory"); }
__device__ __forceinline__ void cp_wait0()  { asm volatile("cp.async.wait_group 0;" ::: "memory"); }
__device__ __forceinline__ void cp_wait1()  { asm volatile("cp.async.wait_group 1;" ::: "memory"); }

__device__ __forceinline__ void mma16(float& d0, float& d1, float& d2, float& d3,
                                      uint32_t a0, uint32_t a1, uint32_t a2, uint32_t a3,
                                      uint32_t b0, uint32_t b1) {
    asm volatile(
        "mma.sync.aligned.m16n8k16.row.col.f32.f16.f16.f32 "
        "{%0,%1,%2,%3}, {%4,%5,%6,%7}, {%8,%9}, {%0,%1,%2,%3};"
        : "+f"(d0), "+f"(d1), "+f"(d2), "+f"(d3)
        : "r"(a0), "r"(a1), "r"(a2), "r"(a3), "r"(b0), "r"(b1));
}
__device__ __forceinline__ void ldsm4(uint32_t& r0, uint32_t& r1, uint32_t& r2,
                                      uint32_t& r3, uint32_t addr) {
    asm volatile("ldmatrix.sync.aligned.m8n8.x4.shared.b16 {%0,%1,%2,%3}, [%4];"
                 : "=r"(r0), "=r"(r1), "=r"(r2), "=r"(r3) : "r"(addr));
}

// ---------------------------------------------------------------------------
// ht_prep: grid 64 (one CTA per o23), 256 threads. (R9-proven, same rounding)
// factors [p][in][out][r] (512,64,8,1); cores: c0=C04, c1=C02, c2=C24
// ---------------------------------------------------------------------------
__global__ void ht_prep(const float* __restrict__ factors,
                        const float* __restrict__ cores) {
    __shared__ float sf[2048];
    __shared__ float sc[1536];
    __shared__ float w23s[512];      // [i23][r24] for this o23
    const int tid = threadIdx.x, blk = blockIdx.x;   // blk = o23
    for (int i = tid; i < 2048; i += 256) sf[i] = factors[i];
    for (int i = tid; i < 1536; i += 256) sc[i] = cores[i];
    __syncthreads();

    #pragma unroll
    for (int j = 0; j < 2; ++j) {
        int e = blk * 512 + j * 256 + tid;
        int row = e >> 6, i01 = e & 63;
        int o01 = row >> 3, r02 = row & 7;
        int o0 = o01 >> 3, o1 = o01 & 7, i0 = i01 >> 3, i1 = i01 & 7;
        const float* F0 = sf + i0 * 64 + o0 * 8;
        const float* F1 = sf + 512 + i1 * 64 + o1 * 8;
        const float* C02 = sc + 512;
        float acc = 0.f;
        #pragma unroll
        for (int r01 = 0; r01 < 8; ++r01) {
            float s = 0.f;
            #pragma unroll
            for (int r12 = 0; r12 < 8; ++r12)
                s += F1[r12] * C02[r01 * 64 + r12 * 8 + r02];
            acc += F0[r01] * s;
        }
        g_W01h[e] = __float2half_rn(acc);
    }

    const int o2 = blk >> 3, o3 = blk & 7;
    #pragma unroll
    for (int j = 0; j < 2; ++j) {
        int t = tid + j * 256;
        int i23 = t >> 3, r24 = t & 7;
        int i2 = i23 >> 3, i3 = i23 & 7;
        const float* F2 = sf + 1024 + i2 * 64 + o2 * 8;
        const float* F3 = sf + 1536 + i3 * 64 + o3 * 8;
        const float* C24 = sc + 1024;
        float acc = 0.f;
        #pragma unroll
        for (int r23 = 0; r23 < 8; ++r23) {
            float s = 0.f;
            #pragma unroll
            for (int r34 = 0; r34 < 8; ++r34)
                s += F3[r34] * C24[r23 * 64 + r34 * 8 + r24];
            acc += F2[r23] * s;
        }
        w23s[t] = acc;
    }
    __syncthreads();

    const float* C04 = sc;
    #pragma unroll
    for (int it = 0; it < 16; ++it) {
        int idx = it * 256 + tid;
        int r02 = idx >> 9, rem = idx & 511;
        int i23 = rem >> 3, r04 = rem & 7;
        const float* w = w23s + i23 * 8;
        const float* c = C04 + r02 * 64 + r04;
        float acc = 0.f;
        #pragma unroll
        for (int r24 = 0; r24 < 8; ++r24) acc += w[r24] * c[r24 * 8];
        int n = blk * 8 + r04, k = r02 * 64 + i23;
        g_Vth[(size_t)n * 512 + k] = __float2half_rn(acc);
    }
}

// ---------------------------------------------------------------------------
// ht_k1m: batched-persistent. grid (2, 128), 256 thr = 8 warps (4m x 2n).
// CTA: load W01h slice [mhalf*256,+256) ONCE; loop 4 batches with
// double-buffered raw-X cp.async prefetch; convert; mma; COALESCED store
// (acc -> smem stage (stride 72, 16B-aligned rows) -> 16B STG).
// SMEM (bytes): W half[256][72]        [0, 36864)
//               Xraw float[2][4096]    [36864, 69632)
//               Bs half[64][72]        [69632, 78848)
//               Tst half[256][72]      [78848, 115712)
// ---------------------------------------------------------------------------
#define K1_XRAW_OFF 36864
#define K1_BS_OFF   69632
#define K1_TST_OFF  78848
#define K1_TST_STRIDE 72
#define K1_SMEM     (78848 + 256 * K1_TST_STRIDE * 2)      // 115712

__global__ __launch_bounds__(256, 2) void ht_k1m(const float* __restrict__ x) {
    extern __shared__ char smc[];
    uint32_t sbase = smem_u32(smc);
    __half* Bs = (__half*)(smc + K1_BS_OFF);
    const float* Xraw = (const float*)(smc + K1_XRAW_OFF);
    const int tid = threadIdx.x, wid = tid >> 5, lane = tid & 31;
    const int gid = lane >> 2, tig = lane & 3;
    const int wm = wid & 3, wn = wid >> 2;
    const int mhalf = blockIdx.x;
    const int b0 = blockIdx.y * 4;

    // group 0: A slice + Xraw[0]
    const __half* Ag = g_W01h + (size_t)(mhalf * 256) * 64;
    #pragma unroll
    for (int i = 0; i < 8; ++i) {
        int l = tid + i * 256;
        int row = l >> 3, s16 = (l & 7) * 8;
        cp16(sbase + (uint32_t)(row * 72 + s16) * 2, Ag + row * 64 + s16);
    }
    {
        const float* xb = x + (size_t)b0 * 4096;
        #pragma unroll
        for (int i = 0; i < 4; ++i) {
            int l = tid + i * 256;
            cp16(sbase + K1_XRAW_OFF + (uint32_t)l * 16, xb + l * 4);
        }
    }
    cp_commit();
    // group 1: Xraw[1]
    {
        const float* xb = x + (size_t)(b0 + 1) * 4096;
        #pragma unroll
        for (int i = 0; i < 4; ++i) {
            int l = tid + i * 256;
            cp16(sbase + K1_XRAW_OFF + 16384 + (uint32_t)l * 16, xb + l * 4);
        }
    }
    cp_commit();

    // ldmatrix lane addressing (byte offsets)
    const uint32_t aoff = ((uint32_t)((wm * 64 + (lane & 7) + ((lane >> 3) & 1) * 8) * 72
                          + ((lane >> 4) & 1) * 8)) * 2;
    const uint32_t boff = (uint32_t)K1_BS_OFF +
                          ((uint32_t)((wn * 32 + (lane & 7) + ((lane >> 4) & 1) * 8) * 72
                          + ((lane >> 3) & 1) * 8)) * 2;

    #pragma unroll 1
    for (int ib = 0; ib < 4; ++ib) {
        const int buf = ib & 1;
        if (ib == 3) cp_wait0(); else cp_wait1();
        __syncthreads();   // Xraw[buf] ready; prior reads of Bs/Tst complete

        // convert Xraw[buf] -> Bs[n=i23][k=i01] fp16 (pairs along i01)
        const float* xr = Xraw + buf * 4096;
        #pragma unroll
        for (int i = 0; i < 8; ++i) {
            int l = tid + i * 256;
            int i23 = l & 63, i01p = (l >> 6) * 2;
            float v0 = xr[i01p * 64 + i23];
            float v1 = xr[(i01p + 1) * 64 + i23];
            *(__half2*)(Bs + i23 * 72 + i01p) = __floats2half2_rn(v0, v1);
        }
        // prefetch next Xraw into buf^1
        if (ib + 2 < 4) {
            const float* xb = x + (size_t)(b0 + ib + 2) * 4096;
            #pragma unroll
            for (int i = 0; i < 4; ++i) {
                int l = tid + i * 256;
                cp16(sbase + K1_XRAW_OFF + (uint32_t)(buf * 16384) + (uint32_t)l * 16,
                     xb + l * 4);
            }
        }
        cp_commit();       // keep group accounting uniform
        __syncthreads();   // Bs ready

        float acc[4][4][4];
        #pragma unroll
        for (int mt = 0; mt < 4; ++mt)
            #pragma unroll
            for (int nt = 0; nt < 4; ++nt)
                #pragma unroll
                for (int q = 0; q < 4; ++q) acc[mt][nt][q] = 0.f;

        #pragma unroll
        for (int s = 0; s < 4; ++s) {
            const uint32_t kb = (uint32_t)(s * 16 * 2);
            uint32_t a[4][4], bf[2][4];
            #pragma unroll
            for (int mt = 0; mt < 4; ++mt)
                ldsm4(a[mt][0], a[mt][1], a[mt][2], a[mt][3],
                      sbase + aoff + (uint32_t)(mt * 16 * 72 * 2) + kb);
            #pragma unroll
            for (int p = 0; p < 2; ++p)
                ldsm4(bf[p][0], bf[p][1], bf[p][2], bf[p][3],
                      sbase + boff + (uint32_t)(p * 16 * 72 * 2) + kb);
            #pragma unroll
            for (int mt = 0; mt < 4; ++mt)
                #pragma unroll
                for (int p = 0; p < 2; ++p) {
                    mma16(acc[mt][2*p][0], acc[mt][2*p][1], acc[mt][2*p][2], acc[mt][2*p][3],
                          a[mt][0], a[mt][1], a[mt][2], a[mt][3], bf[p][0], bf[p][1]);
                    mma16(acc[mt][2*p+1][0], acc[mt][2*p+1][1], acc[mt][2*p+1][2], acc[mt][2*p+1][3],
                          a[mt][0], a[mt][1], a[mt][2], a[mt][3], bf[p][2], bf[p][3]);
                }
        }

        // stage accs into Tst (local rows 0..255, stride 72 halves, 16B-aligned)
        #pragma unroll
        for (int mt = 0; mt < 4; ++mt) {
            int r0 = wm * 64 + mt * 16 + gid;
            #pragma unroll
            for (int nt = 0; nt < 4; ++nt) {
                int col = wn * 32 + nt * 8 + 2 * tig;
                *(__half2*)(smc + K1_TST_OFF + (uint32_t)(r0 * K1_TST_STRIDE + col) * 2) =
                    __floats2half2_rn(acc[mt][nt][0], acc[mt][nt][1]);
                *(__half2*)(smc + K1_TST_OFF + (uint32_t)((r0 + 8) * K1_TST_STRIDE + col) * 2) =
                    __floats2half2_rn(acc[mt][nt][2], acc[mt][nt][3]);
            }
        }
        __syncthreads();   // Tst complete

        // coalesced STG.128: row-major [256][64] halves
        __half* Tb = g_Th + (size_t)(b0 + ib) * 32768 + (size_t)(mhalf * 256) * 64;
        #pragma unroll
        for (int i = 0; i < 8; ++i) {
            int l = tid + i * 256;
            int row = l >> 3, ch = (l & 7) * 8;
            uint4 v = *(const uint4*)(smc + K1_TST_OFF +
                                      (uint32_t)(row * K1_TST_STRIDE + ch) * 2);
            *(uint4*)(Tb + row * 64 + ch) = v;
        }
    }
}

// ---------------------------------------------------------------------------
// ht_k2m: out (32768x512 f32) = Th @ Vth^T.   [R6/R8 proven config]
// grid (4, 256), BM=128 BN=128 BK=64 (halves), 8 warps (4m x 2n),
// warp tile 32m x 64n, 3-stage cp.async, one __syncthreads per chunk.
// ---------------------------------------------------------------------------
#define K2_AH    (128 * 72)                  // halves per matrix per stage
#define K2_STAGE (2 * K2_AH * 2)             // bytes per stage = 36864
#define K2_SMEM  (3 * K2_STAGE)              // 110592 bytes

__device__ __forceinline__ void k2_load(uint32_t sbase, int stage, int c,
                                        int mBase, int nBase, int tid) {
    const __half* Ag = g_Th  + (size_t)mBase * 512 + c * 64;
    const __half* Bg = g_Vth + (size_t)nBase * 512 + c * 64;
    uint32_t ab = sbase + (uint32_t)stage * K2_STAGE;
    uint32_t bb = ab + (uint32_t)K2_AH * 2;
    #pragma unroll
    for (int i = 0; i < 4; ++i) {
        int l = tid + i * 256;
        int row = l >> 3, s16 = (l & 7) * 8;
        cp16(ab + (uint32_t)(row * 72 + s16) * 2, Ag + (size_t)row * 512 + s16);
        cp16(bb + (uint32_t)(row * 72 + s16) * 2, Bg + (size_t)row * 512 + s16);
    }
    cp_commit();
}

__global__ __launch_bounds__(256, 2) void ht_k2m(float* __restrict__ C) {
    extern __shared__ __half smh[];
    uint32_t sbase = smem_u32(smh);
    const int tid = threadIdx.x, wid = tid >> 5, lane = tid & 31;
    const int gid = lane >> 2, tig = lane & 3;
    const int wm = wid & 3, wn = wid >> 2;
    const int mBase = blockIdx.y * 128, nBase = blockIdx.x * 128;

    const uint32_t aoff = ((uint32_t)((wm * 32 + (lane & 7) + ((lane >> 3) & 1) * 8) * 72
                          + ((lane >> 4) & 1) * 8)) * 2;
    const uint32_t boff = (uint32_t)K2_AH * 2 +
                          ((uint32_t)((wn * 64 + (lane & 7) + ((lane >> 4) & 1) * 8) * 72
                          + ((lane >> 3) & 1) * 8)) * 2;

    float acc[2][8][4];
    #pragma unroll
    for (int mt = 0; mt < 2; ++mt)
        #pragma unroll
        for (int nt = 0; nt < 8; ++nt)
            #pragma unroll
            for (int q = 0; q < 4; ++q) acc[mt][nt][q] = 0.f;

    k2_load(sbase, 0, 0, mBase, nBase, tid);
    k2_load(sbase, 1, 1, mBase, nBase, tid);

    #pragma unroll 1
    for (int c = 0; c < 8; ++c) {
        if (c == 7) cp_wait0(); else cp_wait1();
        __syncthreads();
        if (c + 2 < 8) k2_load(sbase, (c + 2) % 3, c + 2, mBase, nBase, tid);

        const uint32_t stb = sbase + (uint32_t)(c % 3) * K2_STAGE;
        const uint32_t ab = stb + aoff;
        const uint32_t bb = stb + boff;
        #pragma unroll
        for (int s = 0; s < 4; ++s) {
            const uint32_t kb = (uint32_t)(s * 16 * 2);
            uint32_t a[2][4], bf[4][4];
            ldsm4(a[0][0], a[0][1], a[0][2], a[0][3], ab + kb);
            ldsm4(a[1][0], a[1][1], a[1][2], a[1][3], ab + kb + 16 * 72 * 2);
            #pragma unroll
            for (int p = 0; p < 4; ++p)
                ldsm4(bf[p][0], bf[p][1], bf[p][2], bf[p][3],
                      bb + kb + (uint32_t)(p * 16 * 72 * 2));
            #pragma unroll
            for (int p = 0; p < 4; ++p) {
                #pragma unroll
                for (int mt = 0; mt < 2; ++mt) {
                    mma16(acc[mt][2*p][0], acc[mt][2*p][1], acc[mt][2*p][2], acc[mt][2*p][3],
                          a[mt][0], a[mt][1], a[mt][2], a[mt][3], bf[p][0], bf[p][1]);
                    mma16(acc[mt][2*p+1][0], acc[mt][2*p+1][1], acc[mt][2*p+1][2], acc[mt][2*p+1][3],
                          a[mt][0], a[mt][1], a[mt][2], a[mt][3], bf[p][2], bf[p][3]);
                }
            }
        }
    }

    #pragma unroll
    for (int mt = 0; mt < 2; ++mt) {
        int r0 = mBase + wm * 32 + mt * 16 + gid;
        #pragma unroll
        for (int nt = 0; nt < 8; ++nt) {
            int col = nBase + wn * 64 + nt * 8 + 2 * tig;
            *(float2*)(C + (size_t)r0 * 512 + col) =
                make_float2(acc[mt][nt][0], acc[mt][nt][1]);
            *(float2*)(C + (size_t)(r0 + 8) * 512 + col) =
                make_float2(acc[mt][nt][2], acc[mt][nt][3]);
        }
    }
}

// ---------------------------------------------------------------------------
extern "C" void kernel_launch(void* const* d_in, const int* in_sizes, int n_in,
                              void* d_out, int out_size) {
    (void)in_sizes; (void)n_in; (void)out_size;
    const float* x       = (const float*)d_in[0];
    const float* factors = (const float*)d_in[1];
    const float* cores   = (const float*)d_in[2];
    float* out = (float*)d_out;

    cudaFuncSetAttribute(ht_k1m, cudaFuncAttributeMaxDynamicSharedMemorySize, K1_SMEM);
    cudaFuncSetAttribute(ht_k2m, cudaFuncAttributeMaxDynamicSharedMemorySize, K2_SMEM);

    ht_prep<<<64, 256>>>(factors, cores);
    ht_k1m<<<dim3(2, 128), 256, K1_SMEM>>>(x);
    ht_k2m<<<dim3(4, 256), 256, K2_SMEM>>>(out);
}

// round 13
// speedup vs baseline: 1.3614x; 1.0758x over previous
#include <cuda_runtime.h>
#include <cuda_fp16.h>
#include <cstdint>

// ---------------------------------------------------------------------------
// HTSubTree, 3-kernel pipeline (fp16 operands, fp32 accumulation):
//   ht_prep : W01h[(o01*8+r02)][i01] (512x64 fp16)
//             Vth[n=(o23*8+r04)][k=(r02*64+i23)] (512x512 fp16)
//   ht_k1m  : Th[b*64+o01][r02*64+i23] = W01h @ X_b^T   (persistent, 4 b/CTA)
//   ht_k2m  : out[b*64+o01][n] = Th @ Vth^T             (R6-proven geometry)
// mma.sync m16n8k16 row.col: A[m][k] row-major, B stored [n][k] n-major.
// ---------------------------------------------------------------------------

__device__ __half g_W01h[512 * 64];
__device__ __half g_Vth[512 * 512];
__device__ __half g_Th[32768 * 512];

// ---------------- helpers --------------------------------------------------
__device__ __forceinline__ uint32_t smem_u32(const void* p) {
    uint32_t a;
    asm("{ .reg .u64 t; cvta.to.shared.u64 t, %1; cvt.u32.u64 %0, t; }" : "=r"(a) : "l"(p));
    return a;
}
__device__ __forceinline__ void cp16(uint32_t s, const void* g) {
    asm volatile("cp.async.cg.shared.global [%0], [%1], 16;" :: "r"(s), "l"(g) : "memory");
}
__device__ __forceinline__ void cp_commit() { asm volatile("cp.async.commit_group;" ::: "memory"); }
__device__ __forceinline__ void cp_wait0()  { asm volatile("cp.async.wait_group 0;" ::: "memory"); }
__device__ __forceinline__ void cp_wait1()  { asm volatile("cp.async.wait_group 1;" ::: "memory"); }

__device__ __forceinline__ void mma16(float& d0, float& d1, float& d2, float& d3,
                                      uint32_t a0, uint32_t a1, uint32_t a2, uint32_t a3,
                                      uint32_t b0, uint32_t b1) {
    asm volatile(
        "mma.sync.aligned.m16n8k16.row.col.f32.f16.f16.f32 "
        "{%0,%1,%2,%3}, {%4,%5,%6,%7}, {%8,%9}, {%0,%1,%2,%3};"
        : "+f"(d0), "+f"(d1), "+f"(d2), "+f"(d3)
        : "r"(a0), "r"(a1), "r"(a2), "r"(a3), "r"(b0), "r"(b1));
}
__device__ __forceinline__ void ldsm4(uint32_t& r0, uint32_t& r1, uint32_t& r2,
                                      uint32_t& r3, uint32_t addr) {
    asm volatile("ldmatrix.sync.aligned.m8n8.x4.shared.b16 {%0,%1,%2,%3}, [%4];"
                 : "=r"(r0), "=r"(r1), "=r"(r2), "=r"(r3) : "r"(addr));
}

// ---------------------------------------------------------------------------
// ht_prep: grid 256 (4 CTAs per o23: blk>>2 = o23, blk&3 = quarter), 256 thr.
// Vectorized float4 loads; W01h split 128/CTA; w23s recomputed per CTA;
// Vth split 1024/CTA (r02 pair per quarter). Per-entry math identical to R12.
// factors [p][in][out][r] (512,64,8,1); cores: c0=C04, c1=C02, c2=C24
// ---------------------------------------------------------------------------
__global__ void ht_prep(const float* __restrict__ factors,
                        const float* __restrict__ cores) {
    __shared__ float sf[2048];
    __shared__ float sc[1536];
    __shared__ float w23s[512];      // [i23][r24] for this o23
    const int tid = threadIdx.x, blk = blockIdx.x;
    const int o23 = blk >> 2, q = blk & 3;

    // vectorized loads: factors = 512 float4, cores = 384 float4
    {
        const float4* f4 = (const float4*)factors;
        float4* sf4 = (float4*)sf;
        sf4[tid] = f4[tid];
        sf4[tid + 256] = f4[tid + 256];
        const float4* c4 = (const float4*)cores;
        float4* sc4 = (float4*)sc;
        sc4[tid] = c4[tid];
        if (tid < 128) sc4[tid + 256] = c4[tid + 256];
    }
    __syncthreads();

    // W01h: 128 entries per CTA (tid < 128), e = blk*128 + tid
    if (tid < 128) {
        int e = blk * 128 + tid;
        int row = e >> 6, i01 = e & 63;
        int o01 = row >> 3, r02 = row & 7;
        int o0 = o01 >> 3, o1 = o01 & 7, i0 = i01 >> 3, i1 = i01 & 7;
        const float* F0 = sf + i0 * 64 + o0 * 8;
        const float* F1 = sf + 512 + i1 * 64 + o1 * 8;
        const float* C02 = sc + 512;
        float acc = 0.f;
        #pragma unroll
        for (int r01 = 0; r01 < 8; ++r01) {
            float s = 0.f;
            #pragma unroll
            for (int r12 = 0; r12 < 8; ++r12)
                s += F1[r12] * C02[r01 * 64 + r12 * 8 + r02];
            acc += F0[r01] * s;
        }
        g_W01h[e] = __float2half_rn(acc);
    }

    // w23s for this o23 (recomputed per CTA; identical formula)
    const int o2 = o23 >> 3, o3 = o23 & 7;
    #pragma unroll
    for (int j = 0; j < 2; ++j) {
        int t = tid + j * 256;
        int i23 = t >> 3, r24 = t & 7;
        int i2 = i23 >> 3, i3 = i23 & 7;
        const float* F2 = sf + 1024 + i2 * 64 + o2 * 8;
        const float* F3 = sf + 1536 + i3 * 64 + o3 * 8;
        const float* C24 = sc + 1024;
        float acc = 0.f;
        #pragma unroll
        for (int r23 = 0; r23 < 8; ++r23) {
            float s = 0.f;
            #pragma unroll
            for (int r34 = 0; r34 < 8; ++r34)
                s += F3[r34] * C24[r23 * 64 + r34 * 8 + r24];
            acc += F2[r23] * s;
        }
        w23s[t] = acc;
    }
    __syncthreads();

    // Vth: quarter q covers r02 in {2q, 2q+1}: idx = q*1024 + j*256 + tid
    const float* C04 = sc;
    #pragma unroll
    for (int j = 0; j < 4; ++j) {
        int idx = q * 1024 + j * 256 + tid;   // 0..4095 within this o23
        int r02 = idx >> 9, rem = idx & 511;
        int i23 = rem >> 3, r04 = rem & 7;
        const float* w = w23s + i23 * 8;
        const float* c = C04 + r02 * 64 + r04;
        float acc = 0.f;
        #pragma unroll
        for (int r24 = 0; r24 < 8; ++r24) acc += w[r24] * c[r24 * 8];
        int n = o23 * 8 + r04, k = r02 * 64 + i23;
        g_Vth[(size_t)n * 512 + k] = __float2half_rn(acc);
    }
}

// ---------------------------------------------------------------------------
// ht_k1m: batched-persistent. grid (2, 128), 256 thr = 8 warps (4m x 2n).
// [R12-proven] W slice loaded once; 4 batches; coalesced Th stores via
// smem stage (stride 72, 16B-aligned rows).
// ---------------------------------------------------------------------------
#define K1_XRAW_OFF 36864
#define K1_BS_OFF   69632
#define K1_TST_OFF  78848
#define K1_TST_STRIDE 72
#define K1_SMEM     (78848 + 256 * K1_TST_STRIDE * 2)      // 115712

__global__ __launch_bounds__(256, 2) void ht_k1m(const float* __restrict__ x) {
    extern __shared__ char smc[];
    uint32_t sbase = smem_u32(smc);
    __half* Bs = (__half*)(smc + K1_BS_OFF);
    const float* Xraw = (const float*)(smc + K1_XRAW_OFF);
    const int tid = threadIdx.x, wid = tid >> 5, lane = tid & 31;
    const int gid = lane >> 2, tig = lane & 3;
    const int wm = wid & 3, wn = wid >> 2;
    const int mhalf = blockIdx.x;
    const int b0 = blockIdx.y * 4;

    const __half* Ag = g_W01h + (size_t)(mhalf * 256) * 64;
    #pragma unroll
    for (int i = 0; i < 8; ++i) {
        int l = tid + i * 256;
        int row = l >> 3, s16 = (l & 7) * 8;
        cp16(sbase + (uint32_t)(row * 72 + s16) * 2, Ag + row * 64 + s16);
    }
    {
        const float* xb = x + (size_t)b0 * 4096;
        #pragma unroll
        for (int i = 0; i < 4; ++i) {
            int l = tid + i * 256;
            cp16(sbase + K1_XRAW_OFF + (uint32_t)l * 16, xb + l * 4);
        }
    }
    cp_commit();
    {
        const float* xb = x + (size_t)(b0 + 1) * 4096;
        #pragma unroll
        for (int i = 0; i < 4; ++i) {
            int l = tid + i * 256;
            cp16(sbase + K1_XRAW_OFF + 16384 + (uint32_t)l * 16, xb + l * 4);
        }
    }
    cp_commit();

    const uint32_t aoff = ((uint32_t)((wm * 64 + (lane & 7) + ((lane >> 3) & 1) * 8) * 72
                          + ((lane >> 4) & 1) * 8)) * 2;
    const uint32_t boff = (uint32_t)K1_BS_OFF +
                          ((uint32_t)((wn * 32 + (lane & 7) + ((lane >> 4) & 1) * 8) * 72
                          + ((lane >> 3) & 1) * 8)) * 2;

    #pragma unroll 1
    for (int ib = 0; ib < 4; ++ib) {
        const int buf = ib & 1;
        if (ib == 3) cp_wait0(); else cp_wait1();
        __syncthreads();

        const float* xr = Xraw + buf * 4096;
        #pragma unroll
        for (int i = 0; i < 8; ++i) {
            int l = tid + i * 256;
            int i23 = l & 63, i01p = (l >> 6) * 2;
            float v0 = xr[i01p * 64 + i23];
            float v1 = xr[(i01p + 1) * 64 + i23];
            *(__half2*)(Bs + i23 * 72 + i01p) = __floats2half2_rn(v0, v1);
        }
        if (ib + 2 < 4) {
            const float* xb = x + (size_t)(b0 + ib + 2) * 4096;
            #pragma unroll
            for (int i = 0; i < 4; ++i) {
                int l = tid + i * 256;
                cp16(sbase + K1_XRAW_OFF + (uint32_t)(buf * 16384) + (uint32_t)l * 16,
                     xb + l * 4);
            }
        }
        cp_commit();
        __syncthreads();

        float acc[4][4][4];
        #pragma unroll
        for (int mt = 0; mt < 4; ++mt)
            #pragma unroll
            for (int nt = 0; nt < 4; ++nt)
                #pragma unroll
                for (int qq = 0; qq < 4; ++qq) acc[mt][nt][qq] = 0.f;

        #pragma unroll
        for (int s = 0; s < 4; ++s) {
            const uint32_t kb = (uint32_t)(s * 16 * 2);
            uint32_t a[4][4], bf[2][4];
            #pragma unroll
            for (int mt = 0; mt < 4; ++mt)
                ldsm4(a[mt][0], a[mt][1], a[mt][2], a[mt][3],
                      sbase + aoff + (uint32_t)(mt * 16 * 72 * 2) + kb);
            #pragma unroll
            for (int p = 0; p < 2; ++p)
                ldsm4(bf[p][0], bf[p][1], bf[p][2], bf[p][3],
                      sbase + boff + (uint32_t)(p * 16 * 72 * 2) + kb);
            #pragma unroll
            for (int mt = 0; mt < 4; ++mt)
                #pragma unroll
                for (int p = 0; p < 2; ++p) {
                    mma16(acc[mt][2*p][0], acc[mt][2*p][1], acc[mt][2*p][2], acc[mt][2*p][3],
                          a[mt][0], a[mt][1], a[mt][2], a[mt][3], bf[p][0], bf[p][1]);
                    mma16(acc[mt][2*p+1][0], acc[mt][2*p+1][1], acc[mt][2*p+1][2], acc[mt][2*p+1][3],
                          a[mt][0], a[mt][1], a[mt][2], a[mt][3], bf[p][2], bf[p][3]);
                }
        }

        #pragma unroll
        for (int mt = 0; mt < 4; ++mt) {
            int r0 = wm * 64 + mt * 16 + gid;
            #pragma unroll
            for (int nt = 0; nt < 4; ++nt) {
                int col = wn * 32 + nt * 8 + 2 * tig;
                *(__half2*)(smc + K1_TST_OFF + (uint32_t)(r0 * K1_TST_STRIDE + col) * 2) =
                    __floats2half2_rn(acc[mt][nt][0], acc[mt][nt][1]);
                *(__half2*)(smc + K1_TST_OFF + (uint32_t)((r0 + 8) * K1_TST_STRIDE + col) * 2) =
                    __floats2half2_rn(acc[mt][nt][2], acc[mt][nt][3]);
            }
        }
        __syncthreads();

        __half* Tb = g_Th + (size_t)(b0 + ib) * 32768 + (size_t)(mhalf * 256) * 64;
        #pragma unroll
        for (int i = 0; i < 8; ++i) {
            int l = tid + i * 256;
            int row = l >> 3, ch = (l & 7) * 8;
            uint4 v = *(const uint4*)(smc + K1_TST_OFF +
                                      (uint32_t)(row * K1_TST_STRIDE + ch) * 2);
            *(uint4*)(Tb + row * 64 + ch) = v;
        }
    }
}

// ---------------------------------------------------------------------------
// ht_k2m: out (32768x512 f32) = Th @ Vth^T.   [R6/R8 proven config]
// ---------------------------------------------------------------------------
#define K2_AH    (128 * 72)
#define K2_STAGE (2 * K2_AH * 2)
#define K2_SMEM  (3 * K2_STAGE)

__device__ __forceinline__ void k2_load(uint32_t sbase, int stage, int c,
                                        int mBase, int nBase, int tid) {
    const __half* Ag = g_Th  + (size_t)mBase * 512 + c * 64;
    const __half* Bg = g_Vth + (size_t)nBase * 512 + c * 64;
    uint32_t ab = sbase + (uint32_t)stage * K2_STAGE;
    uint32_t bb = ab + (uint32_t)K2_AH * 2;
    #pragma unroll
    for (int i = 0; i < 4; ++i) {
        int l = tid + i * 256;
        int row = l >> 3, s16 = (l & 7) * 8;
        cp16(ab + (uint32_t)(row * 72 + s16) * 2, Ag + (size_t)row * 512 + s16);
        cp16(bb + (uint32_t)(row * 72 + s16) * 2, Bg + (size_t)row * 512 + s16);
    }
    cp_commit();
}

__global__ __launch_bounds__(256, 2) void ht_k2m(float* __restrict__ C) {
    extern __shared__ __half smh[];
    uint32_t sbase = smem_u32(smh);
    const int tid = threadIdx.x, wid = tid >> 5, lane = tid & 31;
    const int gid = lane >> 2, tig = lane & 3;
    const int wm = wid & 3, wn = wid >> 2;
    const int mBase = blockIdx.y * 128, nBase = blockIdx.x * 128;

    const uint32_t aoff = ((uint32_t)((wm * 32 + (lane & 7) + ((lane >> 3) & 1) * 8) * 72
                          + ((lane >> 4) & 1) * 8)) * 2;
    const uint32_t boff = (uint32_t)K2_AH * 2 +
                          ((uint32_t)((wn * 64 + (lane & 7) + ((lane >> 4) & 1) * 8) * 72
                          + ((lane >> 3) & 1) * 8)) * 2;

    float acc[2][8][4];
    #pragma unroll
    for (int mt = 0; mt < 2; ++mt)
        #pragma unroll
        for (int nt = 0; nt < 8; ++nt)
            #pragma unroll
            for (int q = 0; q < 4; ++q) acc[mt][nt][q] = 0.f;

    k2_load(sbase, 0, 0, mBase, nBase, tid);
    k2_load(sbase, 1, 1, mBase, nBase, tid);

    #pragma unroll 1
    for (int c = 0; c < 8; ++c) {
        if (c == 7) cp_wait0(); else cp_wait1();
        __syncthreads();
        if (c + 2 < 8) k2_load(sbase, (c + 2) % 3, c + 2, mBase, nBase, tid);

        const uint32_t stb = sbase + (uint32_t)(c % 3) * K2_STAGE;
        const uint32_t ab = stb + aoff;
        const uint32_t bb = stb + boff;
        #pragma unroll
        for (int s = 0; s < 4; ++s) {
            const uint32_t kb = (uint32_t)(s * 16 * 2);
            uint32_t a[2][4], bf[4][4];
            ldsm4(a[0][0], a[0][1], a[0][2], a[0][3], ab + kb);
            ldsm4(a[1][0], a[1][1], a[1][2], a[1][3], ab + kb + 16 * 72 * 2);
            #pragma unroll
            for (int p = 0; p < 4; ++p)
                ldsm4(bf[p][0], bf[p][1], bf[p][2], bf[p][3],
                      bb + kb + (uint32_t)(p * 16 * 72 * 2));
            #pragma unroll
            for (int p = 0; p < 4; ++p) {
                #pragma unroll
                for (int mt = 0; mt < 2; ++mt) {
                    mma16(acc[mt][2*p][0], acc[mt][2*p][1], acc[mt][2*p][2], acc[mt][2*p][3],
                          a[mt][0], a[mt][1], a[mt][2], a[mt][3], bf[p][0], bf[p][1]);
                    mma16(acc[mt][2*p+1][0], acc[mt][2*p+1][1], acc[mt][2*p+1][2], acc[mt][2*p+1][3],
                          a[mt][0], a[mt][1], a[mt][2], a[mt][3], bf[p][2], bf[p][3]);
                }
            }
        }
    }

    #pragma unroll
    for (int mt = 0; mt < 2; ++mt) {
        int r0 = mBase + wm * 32 + mt * 16 + gid;
        #pragma unroll
        for (int nt = 0; nt < 8; ++nt) {
            int col = nBase + wn * 64 + nt * 8 + 2 * tig;
            *(float2*)(C + (size_t)r0 * 512 + col) =
                make_float2(acc[mt][nt][0], acc[mt][nt][1]);
            *(float2*)(C + (size_t)(r0 + 8) * 512 + col) =
                make_float2(acc[mt][nt][2], acc[mt][nt][3]);
        }
    }
}

// ---------------------------------------------------------------------------
extern "C" void kernel_launch(void* const* d_in, const int* in_sizes, int n_in,
                              void* d_out, int out_size) {
    (void)in_sizes; (void)n_in; (void)out_size;
    const float* x       = (const float*)d_in[0];
    const float* factors = (const float*)d_in[1];
    const float* cores   = (const float*)d_in[2];
    float* out = (float*)d_out;

    cudaFuncSetAttribute(ht_k1m, cudaFuncAttributeMaxDynamicSharedMemorySize, K1_SMEM);
    cudaFuncSetAttribute(ht_k2m, cudaFuncAttributeMaxDynamicSharedMemorySize, K2_SMEM);

    ht_prep<<<256, 256>>>(factors, cores);
    ht_k1m<<<dim3(2, 128), 256, K1_SMEM>>>(x);
    ht_k2m<<<dim3(4, 256), 256, K2_SMEM>>>(out);
}